// round 1
// baseline (speedup 1.0000x reference)
#include <cuda_runtime.h>

#define NB 65536
#define FEAT 261
#define HID 128
#define RPW 8            // rows per warp
#define NWARP 8
#define NTHREAD 256
#define GROUP_ROWS (RPW*NWARP)   // 64
#define NGROUP (NB/GROUP_ROWS)   // 1024
#define XS_STRIDE 2112           // per-warp staging floats (>= 261*8, 16B aligned)

// ---- shared memory layout (in floats) ----
#define OFF_WC1 0
#define SZ_WC1 (FEAT*HID)            // 33408
#define OFF_XS  (OFF_WC1 + SZ_WC1)
#define SZ_XS   (NWARP*XS_STRIDE)    // 16896
#define OFF_W0  (OFF_XS + SZ_XS)
#define SZ_W0   288                  // 261 used, zero-padded
#define OFF_W1  (OFF_W0 + SZ_W0)
#define SZ_W1   272                  // 2*133 = 266 used
#define OFF_W2  (OFF_W1 + SZ_W1)
#define SZ_W2   280                  // 4*69 = 276 used
#define OFF_LEAF (OFF_W2 + SZ_W2)
#define SZ_LEAF 64
#define OFF_BC1 (OFF_LEAF + SZ_LEAF) // 128
#define OFF_WC2 (OFF_BC1 + 128)      // 128
#define OFF_B   (OFF_WC2 + 128)      // b0, b1[2], b2[4], bc2
#define SZ_B    8
#define SMEM_FLOATS (OFF_B + SZ_B)
#define SMEM_BYTES  (SMEM_FLOATS*4)

__device__ __forceinline__ float warpsum(float v) {
    v += __shfl_xor_sync(0xffffffffu, v, 16);
    v += __shfl_xor_sync(0xffffffffu, v, 8);
    v += __shfl_xor_sync(0xffffffffu, v, 4);
    v += __shfl_xor_sync(0xffffffffu, v, 2);
    v += __shfl_xor_sync(0xffffffffu, v, 1);
    return v;
}

__device__ __forceinline__ float sigmoidf_fast(float g) {
    return 1.0f / (1.0f + __expf(-g));
}

__global__ void __launch_bounds__(NTHREAD, 1)
ac_kernel(const float* __restrict__ x,
          const float* __restrict__ w0, const float* __restrict__ b0,
          const float* __restrict__ w1, const float* __restrict__ b1,
          const float* __restrict__ w2, const float* __restrict__ b2,
          const float* __restrict__ leaf,
          const float* __restrict__ Wc1, const float* __restrict__ bc1,
          const float* __restrict__ Wc2, const float* __restrict__ bc2,
          float* __restrict__ p_out, float* __restrict__ v_out)
{
    extern __shared__ float sm[];
    const int tid  = threadIdx.x;
    const int lane = tid & 31;
    const int warp = tid >> 5;

    // ---- stage all weights to smem ----
    {
        const float4* g = (const float4*)Wc1;
        float4* s = (float4*)(sm + OFF_WC1);
        #pragma unroll 4
        for (int i = tid; i < SZ_WC1/4; i += NTHREAD) s[i] = g[i];
    }
    for (int i = tid; i < SZ_W0; i += NTHREAD) sm[OFF_W0 + i] = (i < FEAT) ? w0[i] : 0.0f;
    for (int i = tid; i < 266; i += NTHREAD) sm[OFF_W1 + i] = w1[i];
    for (int i = tid; i < 276; i += NTHREAD) sm[OFF_W2 + i] = w2[i];
    if (tid < 64)  sm[OFF_LEAF + tid] = leaf[tid];
    if (tid < 128) sm[OFF_BC1 + tid]  = bc1[tid];
    if (tid < 128) sm[OFF_WC2 + tid]  = Wc2[tid];
    if (tid == 0) {
        sm[OFF_B + 0] = b0[0];
        sm[OFF_B + 1] = b1[0]; sm[OFF_B + 2] = b1[1];
        sm[OFF_B + 3] = b2[0]; sm[OFF_B + 4] = b2[1];
        sm[OFF_B + 5] = b2[2]; sm[OFF_B + 6] = b2[3];
        sm[OFF_B + 7] = bc2[0];
    }
    __syncthreads();

    const float4* wc1_4 = (const float4*)(sm + OFF_WC1);   // [FEAT][32] of float4
    float* xsw = sm + OFF_XS + warp * XS_STRIDE;
    const float4* xs4 = (const float4*)xsw;
    const float4 bcv  = ((const float4*)(sm + OFF_BC1))[lane];
    const float4 wc2v = ((const float4*)(sm + OFF_WC2))[lane];
    const float bc2v  = sm[OFF_B + 7];

    for (int g = blockIdx.x; g < NGROUP; g += gridDim.x) {
        const int row0 = g * GROUP_ROWS + warp * RPW;

        // ---- stage 8 x-rows transposed: xs[f*8 + r] ----
        #pragma unroll
        for (int r = 0; r < RPW; r++) {
            const float* xrow = x + (size_t)(row0 + r) * FEAT;
            #pragma unroll
            for (int k = 0; k < 9; k++) {
                int f = lane + 32*k;
                if (f < FEAT) xsw[f*RPW + r] = xrow[f];
            }
        }
        __syncwarp();

        // ---- decision tree + p (per row; x read from global, L1/L2 hot) ----
        #pragma unroll 1
        for (int r = 0; r < RPW; r++) {
            const int row = row0 + r;
            const float* xrow = x + (size_t)row * FEAT;

            // level 0: full 261-dot with w0
            float part = 0.0f;
            #pragma unroll
            for (int k = 0; k < 9; k++) {
                int f = lane + 32*k;
                if (f < FEAT) part = fmaf(xrow[f], sm[OFF_W0 + f], part);
            }
            float gate = warpsum(part) + sm[OFF_B + 0];
            float cum  = sigmoidf_fast(gate);
            int node   = (gate >= 0.0f) ? 1 : 0;

            // level 1: x5 + 128-slice starting at 5 + node*128
            {
                const float* wr = sm + OFF_W1 + node * 133;
                const int s1 = 5 + node * 128;
                part = (lane < 5) ? xrow[lane] * wr[lane] : 0.0f;
                #pragma unroll
                for (int k = 0; k < 4; k++) {
                    int j = lane + 32*k;
                    part = fmaf(xrow[s1 + j], wr[5 + j], part);
                }
                gate = warpsum(part) + sm[OFF_B + 1 + node];
                cum *= sigmoidf_fast(gate);
                node = node * 2 + ((gate >= 0.0f) ? 1 : 0);
            }
            // level 2: x5 + 64-slice starting at 5 + node*64
            {
                const float* wr = sm + OFF_W2 + node * 69;
                const int s2 = 5 + node * 64;
                part = (lane < 5) ? xrow[lane] * wr[lane] : 0.0f;
                #pragma unroll
                for (int k = 0; k < 2; k++) {
                    int j = lane + 32*k;
                    part = fmaf(xrow[s2 + j], wr[5 + j], part);
                }
                gate = warpsum(part) + sm[OFF_B + 3 + node];
                cum *= sigmoidf_fast(gate);
                node = node * 2 + ((gate >= 0.0f) ? 1 : 0);
            }

            if (lane < 8)
                p_out[(size_t)row * 8 + lane] = cum * sm[OFF_LEAF + node * 8 + lane];
        }

        // ---- critic GEMM: hid = relu(x@Wc1 + bc1); v = hid@Wc2 + bc2 ----
        // lane owns hidden units [4*lane, 4*lane+4); 8 rows register-blocked
        float4 acc[RPW];
        #pragma unroll
        for (int r = 0; r < RPW; r++) acc[r] = bcv;

        #pragma unroll 3
        for (int f = 0; f < FEAT; f++) {
            const float4 w  = wc1_4[f*32 + lane];   // 512B/warp, conflict-free
            const float4 xa = xs4[f*2];             // broadcast
            const float4 xb = xs4[f*2 + 1];         // broadcast
            const float xv[RPW] = {xa.x, xa.y, xa.z, xa.w, xb.x, xb.y, xb.z, xb.w};
            #pragma unroll
            for (int r = 0; r < RPW; r++) {
                acc[r].x = fmaf(xv[r], w.x, acc[r].x);
                acc[r].y = fmaf(xv[r], w.y, acc[r].y);
                acc[r].z = fmaf(xv[r], w.z, acc[r].z);
                acc[r].w = fmaf(xv[r], w.w, acc[r].w);
            }
        }

        #pragma unroll
        for (int r = 0; r < RPW; r++) {
            float vp = fmaf(fmaxf(acc[r].x, 0.0f), wc2v.x,
                       fmaf(fmaxf(acc[r].y, 0.0f), wc2v.y,
                       fmaf(fmaxf(acc[r].z, 0.0f), wc2v.z,
                            fmaxf(acc[r].w, 0.0f) * wc2v.w)));
            vp = warpsum(vp);
            if (lane == 0) v_out[row0 + r] = vp + bc2v;
        }
    }
}

extern "C" void kernel_launch(void* const* d_in, const int* in_sizes, int n_in,
                              void* d_out, int out_size) {
    (void)in_sizes; (void)n_in; (void)out_size;
    const float* x    = (const float*)d_in[0];
    const float* w0   = (const float*)d_in[1];
    const float* b0   = (const float*)d_in[2];
    const float* w1   = (const float*)d_in[3];
    const float* b1   = (const float*)d_in[4];
    const float* w2   = (const float*)d_in[5];
    const float* b2   = (const float*)d_in[6];
    const float* leaf = (const float*)d_in[7];
    const float* Wc1  = (const float*)d_in[8];
    const float* bc1  = (const float*)d_in[9];
    const float* Wc2  = (const float*)d_in[10];
    const float* bc2  = (const float*)d_in[11];

    float* out   = (float*)d_out;
    float* p_out = out;                       // (B, 8)
    float* v_out = out + (size_t)NB * 8;      // (B, 1)

    cudaFuncSetAttribute(ac_kernel, cudaFuncAttributeMaxDynamicSharedMemorySize, SMEM_BYTES);
    ac_kernel<<<NGROUP, NTHREAD, SMEM_BYTES>>>(
        x, w0, b0, w1, b1, w2, b2, leaf, Wc1, bc1, Wc2, bc2, p_out, v_out);
}

// round 3
// speedup vs baseline: 2.1998x; 2.1998x over previous
#include <cuda_runtime.h>
#include <cuda_bf16.h>
#include <cstdint>

#define NB 65536
#define FEAT 261
#define HID 128
#define KSTEPS 17               // ceil(261/16), K padded to 272
#define NTHREAD 512
#define NWARP 16
#define ROWS_CTA 128
#define NCTA (NB / ROWS_CTA)    // 512
#define NTILES_HALF 8           // n-tiles (n8) per n-half (64 cols)

// W fragment scratch: [kstep][ntile(16)][lane(32)][reg(2)] uint32 (2 bf16 each)
#define WFRAG_U32 (KSTEPS * 16 * 32 * 2)      // 17408 u32 = 69632 B
__device__ __align__(16) uint32_t g_whi[WFRAG_U32];
__device__ __align__(16) uint32_t g_wlo[WFRAG_U32];

// ---- smem layout (bytes) ----
#define OFF_PARAMS 0
#define PARAM_FLOATS 1344
#define OFF_WHI  (PARAM_FLOATS * 4)            // 5376
#define OFF_WLO  (OFF_WHI + WFRAG_U32 * 4)     // 5376 + 69632
#define SMEM_BYTES (OFF_WLO + WFRAG_U32 * 4)   // 144640

// float indices inside params region
#define P_W0   0      // 288 (padded; 261 used)
#define P_W1   288    // 266
#define P_W2   554    // 276
#define P_LEAF 830    // 64
#define P_BC1  896    // 128
#define P_WC2  1024   // 128
#define P_B    1152   // b0, b1[2], b2[4], bc2
#define P_VBUF 1160   // 128 row partials
// end 1288 < 1344

// ======================= prep: Wc1 -> bf16 hi/lo fragments =======================
__global__ void __launch_bounds__(256) prep_w(const float* __restrict__ Wc1) {
    int idx = blockIdx.x * 256 + threadIdx.x;   // over WFRAG_U32 entries
    if (idx >= WFRAG_U32) return;
    int reg  = idx & 1;
    int lane = (idx >> 1) & 31;
    int t    = (idx >> 6) & 15;
    int s    = idx >> 10;
    int n = t * 8 + (lane >> 2);
    int k = s * 16 + reg * 8 + (lane & 3) * 2;
    float v0 = (k     < FEAT) ? Wc1[k * HID + n]       : 0.0f;
    float v1 = (k + 1 < FEAT) ? Wc1[(k + 1) * HID + n] : 0.0f;
    __nv_bfloat16 h0 = __float2bfloat16(v0), h1 = __float2bfloat16(v1);
    float r0 = v0 - __bfloat162float(h0), r1 = v1 - __bfloat162float(h1);
    __nv_bfloat16 l0 = __float2bfloat16(r0), l1 = __float2bfloat16(r1);
    g_whi[idx] = ((uint32_t)__bfloat16_as_ushort(h1) << 16) | __bfloat16_as_ushort(h0);
    g_wlo[idx] = ((uint32_t)__bfloat16_as_ushort(l1) << 16) | __bfloat16_as_ushort(l0);
}

// ======================= helpers =======================
__device__ __forceinline__ float warpsum(float v) {
    v += __shfl_xor_sync(0xffffffffu, v, 16);
    v += __shfl_xor_sync(0xffffffffu, v, 8);
    v += __shfl_xor_sync(0xffffffffu, v, 4);
    v += __shfl_xor_sync(0xffffffffu, v, 2);
    v += __shfl_xor_sync(0xffffffffu, v, 1);
    return v;
}
__device__ __forceinline__ float sigmoidf_fast(float g) { return 1.0f / (1.0f + __expf(-g)); }

__device__ __forceinline__ uint32_t pack_hi(float v0, float v1, uint32_t& lo) {
    __nv_bfloat16 h0 = __float2bfloat16(v0), h1 = __float2bfloat16(v1);
    float r0 = v0 - __bfloat162float(h0), r1 = v1 - __bfloat162float(h1);
    __nv_bfloat16 l0 = __float2bfloat16(r0), l1 = __float2bfloat16(r1);
    lo = ((uint32_t)__bfloat16_as_ushort(l1) << 16) | __bfloat16_as_ushort(l0);
    return ((uint32_t)__bfloat16_as_ushort(h1) << 16) | __bfloat16_as_ushort(h0);
}

#define MMA16816(c, a0, a1, a2, a3, b0, b1) \
    asm volatile("mma.sync.aligned.m16n8k16.row.col.f32.bf16.bf16.f32 " \
        "{%0,%1,%2,%3}, {%4,%5,%6,%7}, {%8,%9}, {%0,%1,%2,%3};" \
        : "+f"((c)[0]), "+f"((c)[1]), "+f"((c)[2]), "+f"((c)[3]) \
        : "r"(a0), "r"(a1), "r"(a2), "r"(a3), "r"(b0), "r"(b1))

// ======================= main fused kernel =======================
__global__ void __launch_bounds__(NTHREAD, 1)
ac_main(const float* __restrict__ x,
        const float* __restrict__ w0, const float* __restrict__ b0,
        const float* __restrict__ w1, const float* __restrict__ b1,
        const float* __restrict__ w2, const float* __restrict__ b2,
        const float* __restrict__ leaf,
        const float* __restrict__ bc1,
        const float* __restrict__ Wc2, const float* __restrict__ bc2,
        float* __restrict__ p_out, float* __restrict__ v_out)
{
    extern __shared__ char smem[];
    float* sp = (float*)(smem + OFF_PARAMS);
    const int tid  = threadIdx.x;
    const int lane = tid & 31;
    const int warp = tid >> 5;
    const int row0 = blockIdx.x * ROWS_CTA;

    // ---- stage params ----
    for (int i = tid; i < 288; i += NTHREAD) sp[P_W0 + i] = (i < FEAT) ? w0[i] : 0.0f;
    for (int i = tid; i < 266; i += NTHREAD) sp[P_W1 + i] = w1[i];
    for (int i = tid; i < 276; i += NTHREAD) sp[P_W2 + i] = w2[i];
    if (tid < 64)  sp[P_LEAF + tid] = leaf[tid];
    if (tid < 128) sp[P_BC1 + tid]  = bc1[tid];
    if (tid < 128) sp[P_WC2 + tid]  = Wc2[tid];
    if (tid < 128) sp[P_VBUF + tid] = 0.0f;
    if (tid == 0) {
        sp[P_B + 0] = b0[0];
        sp[P_B + 1] = b1[0]; sp[P_B + 2] = b1[1];
        sp[P_B + 3] = b2[0]; sp[P_B + 4] = b2[1]; sp[P_B + 5] = b2[2]; sp[P_B + 6] = b2[3];
        sp[P_B + 7] = bc2[0];
    }
    // ---- stage W fragments (hi/lo) into smem ----
    {
        const float4* gh = (const float4*)g_whi;
        const float4* gl = (const float4*)g_wlo;
        float4* shh = (float4*)(smem + OFF_WHI);
        float4* sll = (float4*)(smem + OFF_WLO);
        #pragma unroll 4
        for (int i = tid; i < WFRAG_U32 / 4; i += NTHREAD) { shh[i] = gh[i]; sll[i] = gl[i]; }
    }
    __syncthreads();

    // ================= decision tree (exact fp32): 8 rows per warp =================
    {
        const int trow0 = row0 + warp * 8;
        #pragma unroll 1
        for (int r = 0; r < 8; r++) {
            const int row = trow0 + r;
            const float* xrow = x + (size_t)row * FEAT;
            float part = 0.0f;
            #pragma unroll
            for (int k = 0; k < 9; k++) {
                int f = lane + 32 * k;
                if (f < FEAT) part = fmaf(xrow[f], sp[P_W0 + f], part);
            }
            float gate = warpsum(part) + sp[P_B + 0];
            float cum  = sigmoidf_fast(gate);
            int node   = (gate >= 0.0f) ? 1 : 0;
            {
                const float* wr = sp + P_W1 + node * 133;
                const int s1 = 5 + node * 128;
                part = (lane < 5) ? xrow[lane] * wr[lane] : 0.0f;
                #pragma unroll
                for (int k = 0; k < 4; k++) { int j = lane + 32 * k; part = fmaf(xrow[s1 + j], wr[5 + j], part); }
                gate = warpsum(part) + sp[P_B + 1 + node];
                cum *= sigmoidf_fast(gate);
                node = node * 2 + ((gate >= 0.0f) ? 1 : 0);
            }
            {
                const float* wr = sp + P_W2 + node * 69;
                const int s2 = 5 + node * 64;
                part = (lane < 5) ? xrow[lane] * wr[lane] : 0.0f;
                #pragma unroll
                for (int k = 0; k < 2; k++) { int j = lane + 32 * k; part = fmaf(xrow[s2 + j], wr[5 + j], part); }
                gate = warpsum(part) + sp[P_B + 3 + node];
                cum *= sigmoidf_fast(gate);
                node = node * 2 + ((gate >= 0.0f) ? 1 : 0);
            }
            if (lane < 8)
                p_out[(size_t)row * 8 + lane] = cum * sp[P_LEAF + node * 8 + lane];
        }
    }

    // ================= critic GEMM via mma.sync (bf16 hi/lo, 3 passes) =================
    // warp grid: 8 m-tiles (m16) x 2 n-halves (n64). warp = mt*2 + nh.
    const int mt = warp >> 1;
    const int nh = warp & 1;
    const int arow = row0 + mt * 16 + (lane >> 2);   // rows arow, arow+8
    const float* xr0 = x + (size_t)arow * FEAT;
    const float* xr1 = xr0 + (size_t)8 * FEAT;
    const int kbase = (lane & 3) * 2;

    const uint32_t* swhi = (const uint32_t*)(smem + OFF_WHI);
    const uint32_t* swlo = (const uint32_t*)(smem + OFF_WLO);

    float acc[NTILES_HALF][4];
    #pragma unroll
    for (int t = 0; t < NTILES_HALF; t++)
        #pragma unroll
        for (int j = 0; j < 4; j++) acc[t][j] = 0.0f;

    #pragma unroll 1
    for (int s = 0; s < KSTEPS; s++) {
        const int k0 = s * 16 + kbase;
        float a00, a01, a10, a11, a20, a21, a30, a31;
        if (s < 16) {
            a00 = xr0[k0];     a01 = xr0[k0 + 1];
            a10 = xr1[k0];     a11 = xr1[k0 + 1];
            a20 = xr0[k0 + 8]; a21 = xr0[k0 + 9];
            a30 = xr1[k0 + 8]; a31 = xr1[k0 + 9];
        } else {
            a00 = (k0     < FEAT) ? xr0[k0]     : 0.0f;
            a01 = (k0 + 1 < FEAT) ? xr0[k0 + 1] : 0.0f;
            a10 = (k0     < FEAT) ? xr1[k0]     : 0.0f;
            a11 = (k0 + 1 < FEAT) ? xr1[k0 + 1] : 0.0f;
            a20 = (k0 + 8 < FEAT) ? xr0[k0 + 8] : 0.0f;
            a21 = (k0 + 9 < FEAT) ? xr0[k0 + 9] : 0.0f;
            a30 = (k0 + 8 < FEAT) ? xr1[k0 + 8] : 0.0f;
            a31 = (k0 + 9 < FEAT) ? xr1[k0 + 9] : 0.0f;
        }
        uint32_t ah[4], al[4];
        ah[0] = pack_hi(a00, a01, al[0]);
        ah[1] = pack_hi(a10, a11, al[1]);
        ah[2] = pack_hi(a20, a21, al[2]);
        ah[3] = pack_hi(a30, a31, al[3]);

        const uint32_t base = ((uint32_t)s * 16 + nh * NTILES_HALF) * 64 + lane * 2;
        #pragma unroll
        for (int t = 0; t < NTILES_HALF; t++) {
            const uint32_t o = base + (uint32_t)t * 64;
            uint32_t bh0 = swhi[o], bh1 = swhi[o + 1];
            MMA16816(acc[t], ah[0], ah[1], ah[2], ah[3], bh0, bh1);
            MMA16816(acc[t], al[0], al[1], al[2], al[3], bh0, bh1);
            uint32_t bl0 = swlo[o], bl1 = swlo[o + 1];
            MMA16816(acc[t], ah[0], ah[1], ah[2], ah[3], bl0, bl1);
        }
    }

    // ---- epilogue: v-partials = sum_n relu(D + bc1) * Wc2 ----
    float p0 = 0.0f, p1 = 0.0f;   // rows arow, arow+8
    #pragma unroll
    for (int t = 0; t < NTILES_HALF; t++) {
        const int c0 = nh * 64 + t * 8 + (lane & 3) * 2;
        const float b0v = sp[P_BC1 + c0],     w0v = sp[P_WC2 + c0];
        const float b1v = sp[P_BC1 + c0 + 1], w1v = sp[P_WC2 + c0 + 1];
        p0 = fmaf(fmaxf(acc[t][0] + b0v, 0.0f), w0v, p0);
        p0 = fmaf(fmaxf(acc[t][1] + b1v, 0.0f), w1v, p0);
        p1 = fmaf(fmaxf(acc[t][2] + b0v, 0.0f), w0v, p1);
        p1 = fmaf(fmaxf(acc[t][3] + b1v, 0.0f), w1v, p1);
    }
    p0 += __shfl_xor_sync(0xffffffffu, p0, 1);
    p0 += __shfl_xor_sync(0xffffffffu, p0, 2);
    p1 += __shfl_xor_sync(0xffffffffu, p1, 1);
    p1 += __shfl_xor_sync(0xffffffffu, p1, 2);
    if ((lane & 3) == 0) {
        const int lr = mt * 16 + (lane >> 2);
        atomicAdd(&sp[P_VBUF + lr], p0);
        atomicAdd(&sp[P_VBUF + lr + 8], p1);
    }
    __syncthreads();
    if (tid < ROWS_CTA)
        v_out[row0 + tid] = sp[P_VBUF + tid] + sp[P_B + 7];
}

extern "C" void kernel_launch(void* const* d_in, const int* in_sizes, int n_in,
                              void* d_out, int out_size) {
    (void)in_sizes; (void)n_in; (void)out_size;
    const float* x    = (const float*)d_in[0];
    const float* w0   = (const float*)d_in[1];
    const float* b0   = (const float*)d_in[2];
    const float* w1   = (const float*)d_in[3];
    const float* b1   = (const float*)d_in[4];
    const float* w2   = (const float*)d_in[5];
    const float* b2   = (const float*)d_in[6];
    const float* leaf = (const float*)d_in[7];
    const float* Wc1  = (const float*)d_in[8];
    const float* bc1  = (const float*)d_in[9];
    const float* Wc2  = (const float*)d_in[10];
    const float* bc2  = (const float*)d_in[11];

    float* out   = (float*)d_out;
    float* p_out = out;
    float* v_out = out + (size_t)NB * 8;

    prep_w<<<(WFRAG_U32 + 255) / 256, 256>>>(Wc1);

    cudaFuncSetAttribute(ac_main, cudaFuncAttributeMaxDynamicSharedMemorySize, SMEM_BYTES);
    ac_main<<<NCTA, NTHREAD, SMEM_BYTES>>>(
        x, w0, b0, w1, b1, w2, b2, leaf, bc1, Wc2, bc2, p_out, v_out);
}